// round 11
// baseline (speedup 1.0000x reference)
#include <cuda_runtime.h>
#include <cuda_fp16.h>
#include <math.h>

// b=8, c=192, h=w=128, heads=8, ch=24, hw=16384, 3c=576
#define HW 16384
#define C3 576
#define CC 192
#define NB 8
#define QKCH 16

// Scratch (allocation-free rule: __device__ globals)
__device__ __half   g_qkv_pre[75497472];   // [8,576,16384] fp16
__device__ __half   g_qkv_post[75497472];  // [8,576,16384] fp16
__device__ unsigned g_wh[576 * 96];        // packed w_qkv
__device__ unsigned g_W2h[8 * 192 * 96];   // packed folded proj*attn
__device__ float    g_sumsq[8 * 384];
__device__ float    g_Spart[64 * QKCH * 576];

// ---------------------------------------------------------------------------
__device__ __forceinline__ unsigned pkh(float x, float y) {
    __half2 p = __floats2half2_rn(x, y);
    return *(unsigned*)&p;
}
__device__ __forceinline__ unsigned long long splat2(float v) {
    unsigned long long r;
    asm("mov.b64 %0, {%1, %1};" : "=l"(r) : "r"(__float_as_uint(v)));
    return r;
}
__device__ __forceinline__ unsigned long long pk2(float2 v) {
    unsigned long long r;
    asm("mov.b64 %0, {%1, %2};" : "=l"(r)
        : "r"(__float_as_uint(v.x)), "r"(__float_as_uint(v.y)));
    return r;
}
__device__ __forceinline__ void fma2(unsigned long long& acc,
                                     unsigned long long a, unsigned long long b) {
    asm("fma.rn.f32x2 %0, %1, %2, %0;" : "+l"(acc) : "l"(a), "l"(b));
}
__device__ __forceinline__ float2 unpack2(unsigned long long p) {
    unsigned lo, hi;
    asm("mov.b64 {%0, %1}, %2;" : "=r"(lo), "=r"(hi) : "l"(p));
    return make_float2(__uint_as_float(lo), __uint_as_float(hi));
}
__device__ __forceinline__ void mma_f16(float* c, const unsigned* a,
                                        unsigned b0, unsigned b1) {
    asm("mma.sync.aligned.m16n8k16.row.col.f32.f16.f16.f32 "
        "{%0,%1,%2,%3}, {%4,%5,%6,%7}, {%8,%9}, {%0,%1,%2,%3};"
        : "+f"(c[0]), "+f"(c[1]), "+f"(c[2]), "+f"(c[3])
        : "r"(a[0]), "r"(a[1]), "r"(a[2]), "r"(a[3]), "r"(b0), "r"(b1));
}

// ---------------------------------------------------------------------------
// w_qkv fp32 [576][192] -> packed u32 [576][96]
__global__ void presplit_w(const float* __restrict__ w, unsigned* __restrict__ wh)
{
    int i = blockIdx.x * 256 + threadIdx.x;
    if (i >= 576 * 96) return;
    int o = i / 96, j = i % 96;
    float2 v = *(const float2*)&w[o * CC + 2 * j];
    wh[i] = pkh(v.x, v.y);
}

// ---------------------------------------------------------------------------
// B-resident fp16 tensor-core GEMM. K fixed = 192. (proven, unchanged)
#define BST 136   // Bs row stride (u32)
#define AST 100   // As row stride (u32)
#define ABUF (64 * AST)
__global__ __launch_bounds__(256)
void gemm_nres(const unsigned* __restrict__ Apk, long aBS,
               const void* __restrict__ Bv, long bBS,
               void* __restrict__ Ov, long oBS,
               int M, int N, int BMODE, int HALF_OUT)
{
    extern __shared__ unsigned sh[];
    unsigned* Bs = sh;                 // [96][BST]
    unsigned* As = sh + 96 * BST;      // 2 x [64][AST]

    const int b = blockIdx.y;
    const int n0 = blockIdx.x * 128;
    const unsigned* Ab = Apk + aBS * b;
    const int t = threadIdx.x;
    const int wid = t >> 5, lane = t & 31;
    const int g = lane >> 2, tig = lane & 3;
    const int warp_m = wid >> 2, warp_n = wid & 3;

    if (BMODE == 2) {
        const float* Bf = (const float*)Bv + bBS * b;
#pragma unroll
        for (int j = 0; j < 12; j++) {
            int gi = j * 256 + t;
            int pr = gi >> 5;
            int nc = (gi & 31) * 4;
            const float* base = Bf + (long)(2 * pr) * N + n0 + nc;
            float4 u = *(const float4*)base;
            float4 v = *(const float4*)(base + N);
            *(uint4*)&Bs[pr * BST + nc] =
                make_uint4(pkh(u.x, v.x), pkh(u.y, v.y), pkh(u.z, v.z), pkh(u.w, v.w));
        }
    } else {
        const __half* Bh = (const __half*)Bv + bBS * b;
#pragma unroll
        for (int j = 0; j < 12; j++) {
            int gi = j * 256 + t;
            int pr = gi >> 5;
            int nc = (gi & 31) * 4;
            const __half* base = Bh + (long)(2 * pr) * N + n0 + nc;
            uint2 a = *(const uint2*)base;
            uint2 bb = *(const uint2*)(base + N);
            *(uint4*)&Bs[pr * BST + nc] =
                make_uint4(__byte_perm(a.x, bb.x, 0x5410), __byte_perm(a.x, bb.x, 0x7632),
                           __byte_perm(a.y, bb.y, 0x5410), __byte_perm(a.y, bb.y, 0x7632));
        }
    }
#pragma unroll
    for (int j = 0; j < 6; j++) {
        int gi = j * 256 + t;
        int row = gi / 24;
        int kq = (gi % 24) * 4;
        uint4 v = *(const uint4*)&Ab[(long)row * 96 + kq];
        *(uint4*)&As[row * AST + kq] = v;
    }
    __syncthreads();

    const int mtiles = M / 64;
    int buf = 0;
    for (int mt = 0; mt < mtiles; mt++) {
        const int m0 = mt * 64;
        const bool hasNext = (mt + 1 < mtiles);
        uint4 pf[6];
        if (hasNext) {
#pragma unroll
            for (int j = 0; j < 6; j++) {
                int gi = j * 256 + t;
                int row = gi / 24;
                int kq = (gi % 24) * 4;
                pf[j] = *(const uint4*)&Ab[(long)(m0 + 64 + row) * 96 + kq];
            }
        }

        float c[2][4][4];
#pragma unroll
        for (int i = 0; i < 2; i++)
#pragma unroll
            for (int j = 0; j < 4; j++)
#pragma unroll
                for (int q = 0; q < 4; q++) c[i][j][q] = 0.f;

        const unsigned* Ax = As + buf * ABUF;
#pragma unroll
        for (int kp0 = 0; kp0 < 96; kp0 += 8) {
            unsigned a[2][4];
#pragma unroll
            for (int m2 = 0; m2 < 2; m2++) {
                int rb = warp_m * 32 + m2 * 16;
                a[m2][0] = Ax[(rb + g) * AST + kp0 + tig];
                a[m2][1] = Ax[(rb + g + 8) * AST + kp0 + tig];
                a[m2][2] = Ax[(rb + g) * AST + kp0 + tig + 4];
                a[m2][3] = Ax[(rb + g + 8) * AST + kp0 + tig + 4];
            }
#pragma unroll
            for (int nt = 0; nt < 4; nt++) {
                int gc = warp_n * 32 + nt * 8 + g;
                unsigned b0 = Bs[(kp0 + tig) * BST + gc];
                unsigned b1 = Bs[(kp0 + tig + 4) * BST + gc];
#pragma unroll
                for (int m2 = 0; m2 < 2; m2++)
                    mma_f16(c[m2][nt], a[m2], b0, b1);
            }
        }

        if (hasNext) {
#pragma unroll
            for (int j = 0; j < 6; j++) {
                int gi = j * 256 + t;
                int row = gi / 24;
                int kq = (gi % 24) * 4;
                *(uint4*)&As[(buf ^ 1) * ABUF + row * AST + kq] = pf[j];
            }
        }

#pragma unroll
        for (int m2 = 0; m2 < 2; m2++) {
            int row = m0 + warp_m * 32 + m2 * 16 + g;
#pragma unroll
            for (int nt = 0; nt < 4; nt++) {
                int col = n0 + warp_n * 32 + nt * 8 + 2 * tig;
                if (HALF_OUT) {
                    __half* Oh = (__half*)Ov + oBS * b;
                    *(unsigned*)&Oh[(long)row * N + col] =
                        pkh(c[m2][nt][0], c[m2][nt][1]);
                    *(unsigned*)&Oh[(long)(row + 8) * N + col] =
                        pkh(c[m2][nt][2], c[m2][nt][3]);
                } else {
                    float* Of = (float*)Ov + oBS * b;
                    *(float2*)&Of[(long)row * N + col] =
                        make_float2(c[m2][nt][0], c[m2][nt][1]);
                    *(float2*)&Of[(long)(row + 8) * N + col] =
                        make_float2(c[m2][nt][2], c[m2][nt][3]);
                }
            }
        }
        __syncthreads();
        buf ^= 1;
    }
}

// ---------------------------------------------------------------------------
// Depthwise 3x3 conv (dilation 2, pad 2): one block per (ch, b) plane.
// Plane staged as fp32 (converted once), taps via LDS.64 + f32x2 FMA
// (per-lane op order identical to the previous scalar version).
__global__ __launch_bounds__(256)
void dwconv_plane(const __half* __restrict__ in,
                  const float* __restrict__ wdw,
                  __half* __restrict__ out,
                  float* __restrict__ sumsq)
{
    extern __shared__ float spf[];     // 16384 floats = 64 KB
    __shared__ float wred[8];
    const int ch = blockIdx.x;
    const int b  = blockIdx.y;
    const int t  = threadIdx.x;
    const __half* ip = in + ((long)b * C3 + ch) * HW;

    // stage + convert: 8 x (LDG.128 of 8 halves -> 8 floats -> 2 STS.128)
#pragma unroll
    for (int i = 0; i < 8; i++) {
        int off = (i * 256 + t) * 8;
        uint4 v = *(const uint4*)&ip[off];
        float2 f0 = __half22float2(*(__half2*)&v.x);
        float2 f1 = __half22float2(*(__half2*)&v.y);
        float2 f2 = __half22float2(*(__half2*)&v.z);
        float2 f3 = __half22float2(*(__half2*)&v.w);
        *(float4*)&spf[off]     = make_float4(f0.x, f0.y, f1.x, f1.y);
        *(float4*)&spf[off + 4] = make_float4(f2.x, f2.y, f3.x, f3.y);
    }
    unsigned long long w2[9];
#pragma unroll
    for (int i = 0; i < 9; i++) w2[i] = splat2(__ldg(&wdw[ch * 9 + i]));
    __syncthreads();

    unsigned* op = (unsigned*)(out + ((long)b * C3 + ch) * HW);
    float ss = 0.f;

#pragma unroll 4
    for (int i = 0; i < 32; i++) {
        int p = i * 512 + t * 2;        // even pixel index
        int y = p >> 7, x = p & 127;    // x even
        unsigned long long acc = 0ull;
#pragma unroll
        for (int r = 0; r < 3; r++) {
            int yy = y + 2 * (r - 1);
            if (yy < 0 || yy >= 128) continue;
            const float* row = &spf[yy * 128];
            float2 p0 = (x >= 2)   ? *(const float2*)&row[x - 2] : make_float2(0.f, 0.f);
            float2 p1 = *(const float2*)&row[x];
            float2 p2 = (x <= 124) ? *(const float2*)&row[x + 2] : make_float2(0.f, 0.f);
            fma2(acc, w2[r * 3 + 0], pk2(p0));
            fma2(acc, w2[r * 3 + 1], pk2(p1));
            fma2(acc, w2[r * 3 + 2], pk2(p2));
        }
        float2 av = unpack2(acc);
        op[p >> 1] = pkh(av.x, av.y);
        ss += av.x * av.x + av.y * av.y;
    }

    if (ch < 384) {
#pragma unroll
        for (int off = 16; off; off >>= 1)
            ss += __shfl_down_sync(0xffffffffu, ss, off);
        if ((t & 31) == 0) wred[t >> 5] = ss;
        __syncthreads();
        if (t == 0) {
            float s = 0.f;
#pragma unroll
            for (int i = 0; i < 8; i++) s += wred[i];
            sumsq[b * 384 + ch] = s;
        }
    }
}

// ---------------------------------------------------------------------------
// Raw S = q.k^T (24x24 per (b,head)), split-K over QKCH chunks.
// 6x6 register tile over 16-thread groups; 16 spatial slices per block.
// Shfl-combine paired slices in-warp, then 8-slab smem reduction.
#define QKS 132
__global__ __launch_bounds__(256)
void qk_kernel(const __half* __restrict__ qkv, float* __restrict__ Spart)
{
    __shared__ float qs[24 * QKS];
    __shared__ float ks[24 * QKS];
    __shared__ float Sred[8][576];

    const int chunk = blockIdx.x;
    const int bh    = blockIdx.y;
    const int b = bh >> 3, h = bh & 7;
    const __half* qp = qkv + ((long)b * C3 + h * 24) * HW;
    const __half* kp = qkv + ((long)b * C3 + 192 + h * 24) * HW;
    const int t = threadIdx.x;
    const int wp = t >> 4;            // spatial slice 0..15
    const int t16 = t & 15;
    const int cc = (t16 >> 2) * 6;    // 0,6,12,18
    const int dd = (t16 & 3) * 6;     // 0,6,12,18

    unsigned long long a[6][6];
#pragma unroll
    for (int i = 0; i < 6; i++)
#pragma unroll
        for (int j = 0; j < 6; j++) a[i][j] = 0ull;

    int n0 = chunk * (HW / QKCH);
    const int iters = (HW / QKCH) / 128;
    for (int it = 0; it < iters; it++, n0 += 128) {
        // stage: 768 uint4 tasks (q: 0..383, k: 384..767), fp16 -> fp32
#pragma unroll
        for (int j = 0; j < 3; j++) {
            int gi = j * 256 + t;
            int isk = gi >= 384;
            int li = isk ? gi - 384 : gi;
            int r = li >> 4, c16 = li & 15;
            const __half* src = (isk ? kp : qp) + (long)r * HW + n0 + c16 * 8;
            uint4 v = *(const uint4*)src;
            float* dst = (isk ? ks : qs) + r * QKS + c16 * 8;
            float2 f;
            f = __half22float2(*(__half2*)&v.x); *(float2*)&dst[0] = f;
            f = __half22float2(*(__half2*)&v.y); *(float2*)&dst[2] = f;
            f = __half22float2(*(__half2*)&v.z); *(float2*)&dst[4] = f;
            f = __half22float2(*(__half2*)&v.w); *(float2*)&dst[6] = f;
        }
        __syncthreads();

        // slice wp covers spatial [wp*8, wp*8+8): 2 s-steps of 4 columns
#pragma unroll
        for (int s = 0; s < 2; s++) {
            int nb = wp * 8 + s * 4;
            ulonglong2 q[6];
#pragma unroll
            for (int i = 0; i < 6; i++)
                q[i] = *(const ulonglong2*)&qs[(cc + i) * QKS + nb];
#pragma unroll
            for (int j = 0; j < 6; j++) {
                ulonglong2 k = *(const ulonglong2*)&ks[(dd + j) * QKS + nb];
#pragma unroll
                for (int i = 0; i < 6; i++) {
                    fma2(a[i][j], q[i].x, k.x);
                    fma2(a[i][j], q[i].y, k.y);
                }
            }
        }
        __syncthreads();
    }

    // in-warp combine of paired slices (t and t+16 share (cc,dd)), 8 slabs
#pragma unroll
    for (int i = 0; i < 6; i++)
#pragma unroll
        for (int j = 0; j < 6; j++) {
            float2 v = unpack2(a[i][j]);
            float s = v.x + v.y;
            s += __shfl_down_sync(0xffffffffu, s, 16);
            if (t16 == (t & 31))   // lane < 16
                Sred[wp >> 1][(cc + i) * 24 + dd + j] = s;
        }
    __syncthreads();

    float* sp = Spart + ((long)bh * QKCH + chunk) * 576;
    for (int i = t; i < 576; i += 256) {
        float s01 = Sred[0][i] + Sred[1][i];
        float s23 = Sred[2][i] + Sred[3][i];
        float s45 = Sred[4][i] + Sred[5][i];
        float s67 = Sred[6][i] + Sred[7][i];
        sp[i] = (s01 + s23) + (s45 + s67);
    }
}

// ---------------------------------------------------------------------------
// Per (b,head): reduce split-K, normalize, softmax, fold w_proj -> fp16 W2.
__global__ void softmax_fold_kernel(const float* __restrict__ Spart,
                                    const float* __restrict__ sumsq,
                                    const float* __restrict__ temp,
                                    const float* __restrict__ wproj,
                                    unsigned* __restrict__ W2h)
{
    const int bh = blockIdx.x;          // 0..63
    const int b = bh >> 3, h = bh & 7;
    const int t = threadIdx.x;          // 256
    __shared__ float A[576];
    __shared__ float nq[24], nk[24];
    if (t < 24)
        nq[t] = sqrtf(sumsq[b * 384 + h * 24 + t]) + 1e-6f;
    else if (t < 48)
        nk[t - 24] = sqrtf(sumsq[b * 384 + 192 + h * 24 + (t - 24)]) + 1e-6f;
    __syncthreads();
    const float tmp = temp[h];
    for (int r = t; r < 576; r += 256) {
        int cidx = r / 24, d = r % 24;
        float s = 0.f;
#pragma unroll
        for (int ck = 0; ck < QKCH; ck++)
            s += Spart[((long)bh * QKCH + ck) * 576 + r];
        A[r] = s / (nq[cidx] * nk[d]) * tmp;
    }
    __syncthreads();
    if (t < 24) {
        float* row = &A[t * 24];
        float m = row[0];
        for (int d = 1; d < 24; d++) m = fmaxf(m, row[d]);
        float s = 0.f;
        for (int d = 0; d < 24; d++) { float e = expf(row[d] - m); row[d] = e; s += e; }
        float inv = 1.f / s;
        for (int d = 0; d < 24; d++) row[d] *= inv;
    }
    __syncthreads();
    for (int idx = t; idx < 192 * 12; idx += 256) {
        int o = idx / 12, jj = idx % 12;
        int d0 = 2 * jj;
        float s0 = 0.f, s1 = 0.f;
#pragma unroll
        for (int cidx = 0; cidx < 24; cidx++) {
            float wv = wproj[o * CC + h * 24 + cidx];
            s0 += wv * A[cidx * 24 + d0];
            s1 += wv * A[cidx * 24 + d0 + 1];
        }
        W2h[((long)b * CC + o) * 96 + h * 12 + jj] = pkh(s0, s1);
    }
}

// ---------------------------------------------------------------------------
extern "C" void kernel_launch(void* const* d_in, const int* in_sizes, int n_in,
                              void* d_out, int out_size)
{
    const float* x      = (const float*)d_in[0];
    const float* w_qkv  = (const float*)d_in[1];
    const float* w_dw   = (const float*)d_in[2];
    const float* w_proj = (const float*)d_in[3];
    const float* temp   = (const float*)d_in[4];
    float* out = (float*)d_out;

    __half *qkv_pre, *qkv_post;
    unsigned *wh, *W2h;
    float *sumsq, *Spart;
    cudaGetSymbolAddress((void**)&qkv_pre,  g_qkv_pre);
    cudaGetSymbolAddress((void**)&qkv_post, g_qkv_post);
    cudaGetSymbolAddress((void**)&wh,       g_wh);
    cudaGetSymbolAddress((void**)&W2h,      g_W2h);
    cudaGetSymbolAddress((void**)&sumsq,    g_sumsq);
    cudaGetSymbolAddress((void**)&Spart,    g_Spart);

    const int SMEM = (96 * BST + 2 * 64 * AST) * 4;  // 103424 B
    cudaFuncSetAttribute(gemm_nres,
                         cudaFuncAttributeMaxDynamicSharedMemorySize, SMEM);
    const int DWSMEM = 16384 * 4;                    // 65536 B
    cudaFuncSetAttribute(dwconv_plane,
                         cudaFuncAttributeMaxDynamicSharedMemorySize, DWSMEM);

    presplit_w<<<(576 * 96 + 255) / 256, 256>>>(w_qkv, wh);

    // K1: qkv = w_qkv @ x  -> fp16 (B resident, double-buffered A)
    gemm_nres<<<dim3(HW / 128, NB), 256, SMEM>>>(
        wh, 0L, x, (long)CC * HW, qkv_pre, (long)C3 * HW, C3, HW, 2, 1);

    // K2: depthwise conv (fp32 plane in smem, f32x2 taps) + sumsq
    dwconv_plane<<<dim3(C3, NB), 256, DWSMEM>>>(qkv_pre, w_dw, qkv_post, sumsq);

    // K3: q.k^T, 6x6 tile over 16-thread groups
    qk_kernel<<<dim3(QKCH, 64), 256>>>(qkv_post, Spart);

    // K4: per-(b,h) normalize + softmax + fold -> packed fp16 W2
    softmax_fold_kernel<<<64, 256>>>(Spart, sumsq, temp, w_proj, W2h);

    // K5: out = W2 @ v  (B = v resident fp16), fp32 out
    gemm_nres<<<dim3(HW / 128, NB), 256, SMEM>>>(
        W2h, (long)CC * 96, qkv_post + 384L * HW, (long)C3 * HW,
        out, (long)CC * HW, CC, HW, 1, 0);
}